// round 6
// baseline (speedup 1.0000x reference)
#include <cuda_runtime.h>

#define B_SZ   128
#define N_VN   24576
#define N_ITERS 10
#define CLIPV  20.0f
#define TPB    256
#define COMPF  (TPB * 6)
#define SIGNM  0x80000000u
#define L2E    1.4426950408889634f

typedef unsigned long long ull;

__device__ __forceinline__ float mxs_min(float a, float b) {
    float d; asm("min.xorsign.abs.f32 %0, %1, %2;" : "=f"(d) : "f"(a), "f"(b)); return d;
}
__device__ __forceinline__ float mxs_max(float a, float b) {
    float d; asm("max.xorsign.abs.f32 %0, %1, %2;" : "=f"(d) : "f"(a), "f"(b)); return d;
}
__device__ __forceinline__ ull pk2(float lo, float hi) {
    ull r; asm("mov.b64 %0, {%1, %2};" : "=l"(r) : "f"(lo), "f"(hi)); return r;
}
__device__ __forceinline__ void upk2(float& lo, float& hi, ull v) {
    asm("mov.b64 {%0, %1}, %2;" : "=f"(lo), "=f"(hi) : "l"(v));
}
__device__ __forceinline__ ull add2(ull a, ull b) {
    ull r; asm("add.rn.f32x2 %0, %1, %2;" : "=l"(r) : "l"(a), "l"(b)); return r;
}
__device__ __forceinline__ ull mul2(ull a, ull b) {
    ull r; asm("mul.rn.f32x2 %0, %1, %2;" : "=l"(r) : "l"(a), "l"(b)); return r;
}
__device__ __forceinline__ ull fma2(ull a, ull b, ull c) {
    ull r; asm("fma.rn.f32x2 %0, %1, %2, %3;" : "=l"(r) : "l"(a), "l"(b), "l"(c)); return r;
}
__device__ __forceinline__ float ex2f(float x) {
    float r; asm("ex2.approx.ftz.f32 %0, %1;" : "=f"(r) : "f"(x)); return r;
}

__global__ void ldpc_init(float* out) {
    if (threadIdx.x == 0) out[0] = 0.0f;
}

__global__ __launch_bounds__(TPB, 6) void ldpc_decode(
    const float* __restrict__ llr_in,
    const float* __restrict__ cn_weight,
    const float* __restrict__ ch_weight,
    const float* __restrict__ cn_bias,
    float* __restrict__ out)          // out[0]=loss, out+1 = dec [B, N]
{
    __shared__ float sbuf[COMPF];
    __shared__ float sred[TPB / 32];

    const int b    = blockIdx.x >> 4;
    const int blk  = blockIdx.x & 15;
    const int base = b * N_VN + blk * COMPF;
    const int lbase = threadIdx.x * 6;

    {
        const float4* src = reinterpret_cast<const float4*>(llr_in + base);
        float4* dst = reinterpret_cast<float4*>(sbuf);
        for (int i = threadIdx.x; i < COMPF / 4; i += TPB) dst[i] = src[i];
    }
    __syncthreads();

    // llr stays in smem (sbuf) for the whole loop; only psum/c2v live in regs.
    ull psum2[3], nc2v2[3][3];              // nc2v = NEGATED c2v, packed pairs
    #pragma unroll
    for (int i = 0; i < 3; i++) {
        psum2[i] = 0ull;
        nc2v2[0][i] = 0ull; nc2v2[1][i] = 0ull; nc2v2[2][i] = 0ull;
    }

    float racc  = 0.0f;
    float prodA = 1.0f, prodB = 1.0f;
    const ull negone2 = pk2(-1.0f, -1.0f);

    #pragma unroll 1
    for (int it = 0; it < N_ITERS; ++it) {
        const float wch  = __ldg(ch_weight + it);
        const float wcn  = __ldg(cn_weight + it);
        const float bcn  = __ldg(cn_bias + it);
        const float wabs = fabsf(wcn);
        const unsigned wsgnM = __float_as_uint(wcn) & SIGNM;
        const float    wneg  = -wcn;
        const unsigned pbw_u = __float_as_uint(bcn) ^ wsgnM;
        const float capA = fminf(CLIPV, __fdividef(CLIPV + bcn, wabs));
        const float th   = __fdividef(bcn, wabs);
        const ull   wch2 = pk2(wch, wch);

        ull t2[3];
        #pragma unroll
        for (int i = 0; i < 3; i++) {
            const ull l2 = *reinterpret_cast<const ull*>(sbuf + lbase + 2 * i);
            t2[i] = fma2(l2, wch2, psum2[i]);    // t = llr*wch + sum (psum dead after)
        }

        #pragma unroll
        for (int k = 0; k < 3; k++) {
            float v[6];
            #pragma unroll
            for (int i = 0; i < 3; i++) {
                const ull v2 = add2(t2[i], nc2v2[k][i]);      // v = t - c2v
                upk2(v[2 * i], v[2 * i + 1], v2);
            }
            // xorsign tournament: LOO-min magnitude, XOR-accumulated signs.
            const float p01 = mxs_min(v[0], v[1]);
            const float p23 = mxs_min(v[2], v[3]);
            const float p45 = mxs_min(v[4], v[5]);
            const float qc  = mxs_min(mxs_min(p23, p45), capA);
            const float rc  = mxs_min(mxs_min(p01, p45), capA);
            const float sc  = mxs_min(mxs_min(p01, p23), capA);
            float ext[6];
            ext[0] = mxs_max(mxs_min(v[1], qc), th);
            ext[1] = mxs_max(mxs_min(v[0], qc), th);
            ext[2] = mxs_max(mxs_min(v[3], rc), th);
            ext[3] = mxs_max(mxs_min(v[2], rc), th);
            ext[4] = mxs_max(mxs_min(v[5], sc), th);
            ext[5] = mxs_max(mxs_min(v[4], sc), th);

            float nc[6];
            #pragma unroll
            for (int j = 0; j < 6; j++) {
                // nc2v = -c2v = -sgn*(|ext|*wabs - bcn); sgn carried by ext & wcn
                const float aj = __uint_as_float(pbw_u ^ (__float_as_uint(ext[j]) & SIGNM));
                nc[j] = fmaf(ext[j], wneg, aj);
            }
            #pragma unroll
            for (int i = 0; i < 3; i++) nc2v2[k][i] = pk2(nc[2 * i], nc[2 * i + 1]);
        }

        // marginals + BCE pieces (log deferred via split product accumulators)
        #pragma unroll
        for (int i = 0; i < 3; i++) {
            const ull nsum = add2(add2(nc2v2[0][i], nc2v2[1][i]), nc2v2[2][i]);
            psum2[i] = mul2(nsum, negone2);                   // +sum
            const ull l2 = *reinterpret_cast<const ull*>(sbuf + lbase + 2 * i);
            const ull d2 = add2(l2, psum2[i]);
            float d0, d1;
            upk2(d0, d1, d2);
            racc += fmaxf(-d0, 0.0f);
            racc += fmaxf(-d1, 0.0f);
            const float e0 = ex2f(-fabsf(d0 * L2E));          // exp(-|dec|)
            const float e1 = ex2f(-fabsf(d1 * L2E));
            prodA = fmaf(prodA, e0, prodA);                   // *= (1 + e)
            prodB = fmaf(prodB, e1, prodB);
        }
    }

    float loss = fmaf(0.6931471805599453f, __log2f(prodA) + __log2f(prodB), racc);

    // recompute dec, overwrite own smem cells (no cross-thread access -> no
    // sync needed before the overwrite), then coalesced global write
    float dec[6];
    #pragma unroll
    for (int i = 0; i < 3; i++) {
        const ull l2 = *reinterpret_cast<const ull*>(sbuf + lbase + 2 * i);
        const ull d2 = add2(l2, psum2[i]);
        upk2(dec[2 * i], dec[2 * i + 1], d2);
    }
    #pragma unroll
    for (int j = 0; j < 6; j++) sbuf[lbase + j] = dec[j];
    __syncthreads();
    {
        float* dptr = out + 1 + base;
        for (int i = threadIdx.x; i < COMPF; i += TPB) dptr[i] = sbuf[i];
    }

    // loss reduction: warp shuffle -> smem -> one atomic per block
    #pragma unroll
    for (int o = 16; o; o >>= 1) loss += __shfl_xor_sync(0xffffffffu, loss, o);
    if ((threadIdx.x & 31) == 0) sred[threadIdx.x >> 5] = loss;
    __syncthreads();
    if (threadIdx.x == 0) {
        float tot = 0.0f;
        #pragma unroll
        for (int w = 0; w < TPB / 32; w++) tot += sred[w];
        atomicAdd(out, tot * (1.0f / ((float)B_SZ * (float)N_VN)));
    }
}

extern "C" void kernel_launch(void* const* d_in, const int* in_sizes, int n_in,
                              void* d_out, int out_size) {
    const float* llr = (const float*)d_in[0];
    const float* cnw = (const float*)d_in[1];
    const float* chw = (const float*)d_in[2];
    const float* cnb = (const float*)d_in[3];
    float* out = (float*)d_out;
    (void)in_sizes; (void)n_in; (void)out_size;

    ldpc_init<<<1, 32>>>(out);
    ldpc_decode<<<B_SZ * 16, TPB>>>(llr, cnw, chw, cnb, out);
}

// round 7
// speedup vs baseline: 1.8078x; 1.8078x over previous
#include <cuda_runtime.h>

#define B_SZ   128
#define N_VN   24576
#define N_ITERS 10
#define CLIPV  20.0f
#define TPB    256
#define COMPF  (TPB * 6)
#define SIGNM  0x80000000u
#define L2E    1.4426950408889634f

typedef unsigned long long ull;

__device__ __forceinline__ float mxs_min(float a, float b) {
    float d; asm("min.xorsign.abs.f32 %0, %1, %2;" : "=f"(d) : "f"(a), "f"(b)); return d;
}
__device__ __forceinline__ float mxs_max(float a, float b) {
    float d; asm("max.xorsign.abs.f32 %0, %1, %2;" : "=f"(d) : "f"(a), "f"(b)); return d;
}
__device__ __forceinline__ ull pk2(float lo, float hi) {
    ull r; asm("mov.b64 %0, {%1, %2};" : "=l"(r) : "f"(lo), "f"(hi)); return r;
}
__device__ __forceinline__ void upk2(float& lo, float& hi, ull v) {
    asm("mov.b64 {%0, %1}, %2;" : "=f"(lo), "=f"(hi) : "l"(v));
}
__device__ __forceinline__ ull add2(ull a, ull b) {
    ull r; asm("add.rn.f32x2 %0, %1, %2;" : "=l"(r) : "l"(a), "l"(b)); return r;
}
__device__ __forceinline__ ull mul2(ull a, ull b) {
    ull r; asm("mul.rn.f32x2 %0, %1, %2;" : "=l"(r) : "l"(a), "l"(b)); return r;
}
__device__ __forceinline__ ull fma2(ull a, ull b, ull c) {
    ull r; asm("fma.rn.f32x2 %0, %1, %2, %3;" : "=l"(r) : "l"(a), "l"(b), "l"(c)); return r;
}
__device__ __forceinline__ float ex2f(float x) {
    float r; asm("ex2.approx.ftz.f32 %0, %1;" : "=f"(r) : "f"(x)); return r;
}

__global__ void ldpc_init(float* out) {
    if (threadIdx.x == 0) out[0] = 0.0f;
}

__global__ __launch_bounds__(TPB, 5) void ldpc_decode(
    const float* __restrict__ llr_in,
    const float* __restrict__ cn_weight,
    const float* __restrict__ ch_weight,
    const float* __restrict__ cn_bias,
    float* __restrict__ out)          // out[0]=loss, out+1 = dec [B, N]
{
    __shared__ float sbuf[COMPF];
    __shared__ float sred[TPB / 32];
    __shared__ __align__(16) float itc[N_ITERS][8];   // per-iter constants

    const int b    = blockIdx.x >> 4;
    const int blk  = blockIdx.x & 15;
    const int base = b * N_VN + blk * COMPF;

    // per-iteration constants computed ONCE (threads 0..9), before the sync
    if (threadIdx.x < N_ITERS) {
        const int it = threadIdx.x;
        const float wch  = ch_weight[it];
        const float wcn  = cn_weight[it];
        const float bcn  = cn_bias[it];
        const float wabs = fabsf(wcn);
        const unsigned wsgnM = __float_as_uint(wcn) & SIGNM;
        itc[it][0] = wch;
        itc[it][1] = wch;                                   // (wch,wch) f32x2 pair
        itc[it][2] = -wcn;                                  // wneg
        itc[it][3] = __uint_as_float(__float_as_uint(bcn) ^ wsgnM);  // pbw
        itc[it][4] = fminf(CLIPV, (CLIPV + bcn) / wabs);    // capA
        itc[it][5] = bcn / wabs;                            // th
    }

    {
        const float4* src = reinterpret_cast<const float4*>(llr_in + base);
        float4* dst = reinterpret_cast<float4*>(sbuf);
        for (int i = threadIdx.x; i < COMPF / 4; i += TPB) dst[i] = src[i];
    }
    __syncthreads();

    ull llr2[3], psum2[3], nc2v2[3][3];     // nc2v = NEGATED c2v, packed pairs
    #pragma unroll
    for (int i = 0; i < 3; i++) {
        llr2[i]  = pk2(sbuf[threadIdx.x * 6 + 2 * i], sbuf[threadIdx.x * 6 + 2 * i + 1]);
        psum2[i] = 0ull;
        nc2v2[0][i] = 0ull; nc2v2[1][i] = 0ull; nc2v2[2][i] = 0ull;
    }

    float racc  = 0.0f;
    float prodA = 1.0f, prodB = 1.0f;
    const ull negone2 = pk2(-1.0f, -1.0f);
    const ull l2e2    = pk2(L2E, L2E);

    #pragma unroll
    for (int it = 0; it < N_ITERS; ++it) {
        const ull   wch2  = *reinterpret_cast<const ull*>(&itc[it][0]);
        const float wneg  = itc[it][2];
        const unsigned pbw_u = __float_as_uint(itc[it][3]);
        const float capA  = itc[it][4];
        const float th    = itc[it][5];

        ull t2[3];
        #pragma unroll
        for (int i = 0; i < 3; i++) t2[i] = fma2(llr2[i], wch2, psum2[i]);

        #pragma unroll
        for (int k = 0; k < 3; k++) {
            float v[6];
            #pragma unroll
            for (int i = 0; i < 3; i++) {
                const ull v2 = add2(t2[i], nc2v2[k][i]);      // v = t - c2v
                upk2(v[2 * i], v[2 * i + 1], v2);
            }
            // prefix/suffix xorsign LOO-min, cap folded into both scan heads.
            // mxs ops carry magnitude-min + XOR of sign bits; capA/th > 0 are
            // sign-transparent, so ext[j] = sign(prod of other 5) * clamped mag.
            const float q1  = mxs_min(v[0], v[1]);
            const float q1c = mxs_min(q1, capA);
            const float q2  = mxs_min(q1c, v[2]);
            const float q3  = mxs_min(q2,  v[3]);
            const float q4  = mxs_min(q3,  v[4]);
            const float r4  = mxs_min(v[5], v[4]);
            const float r4c = mxs_min(r4, capA);
            const float r3  = mxs_min(r4c, v[3]);
            const float r2  = mxs_min(r3,  v[2]);
            const float r1  = mxs_min(r2,  v[1]);
            float ext[6];
            ext[0] = mxs_max(r1, th);
            ext[1] = mxs_max(mxs_min(v[0], r2), th);
            ext[2] = mxs_max(mxs_min(q1c, r3), th);
            ext[3] = mxs_max(mxs_min(q2, r4c), th);
            ext[4] = mxs_max(mxs_min(q3, v[5]), th);
            ext[5] = mxs_max(q4, th);

            float nc[6];
            #pragma unroll
            for (int j = 0; j < 6; j++) {
                // nc2v = -c2v = -sgn*(|ext|*wabs - bcn); sgn carried by ext & wcn
                const float aj = __uint_as_float(pbw_u ^ (__float_as_uint(ext[j]) & SIGNM));
                nc[j] = fmaf(ext[j], wneg, aj);
            }
            #pragma unroll
            for (int i = 0; i < 3; i++) nc2v2[k][i] = pk2(nc[2 * i], nc[2 * i + 1]);
        }

        // marginals + BCE pieces (log deferred via split product accumulators)
        #pragma unroll
        for (int i = 0; i < 3; i++) {
            const ull nsum = add2(add2(nc2v2[0][i], nc2v2[1][i]), nc2v2[2][i]);
            psum2[i] = mul2(nsum, negone2);                   // +sum
            const ull d2 = add2(llr2[i], psum2[i]);
            float d0, d1;
            upk2(d0, d1, d2);
            racc += fmaxf(-d0, 0.0f);
            racc += fmaxf(-d1, 0.0f);
            float u0, u1;
            upk2(u0, u1, mul2(d2, l2e2));
            const float e0 = ex2f(fminf(u0, -u0));            // exp(-|dec|)
            const float e1 = ex2f(fminf(u1, -u1));
            prodA = fmaf(prodA, e0, prodA);                   // *= (1 + e)
            prodB = fmaf(prodB, e1, prodB);
        }
    }

    float loss = fmaf(0.6931471805599453f, __log2f(prodA) + __log2f(prodB), racc);

    // recompute dec, overwrite own smem cells, then coalesced global write
    #pragma unroll
    for (int i = 0; i < 3; i++) {
        const ull d2 = add2(llr2[i], psum2[i]);
        float d0, d1;
        upk2(d0, d1, d2);
        sbuf[threadIdx.x * 6 + 2 * i]     = d0;
        sbuf[threadIdx.x * 6 + 2 * i + 1] = d1;
    }
    __syncthreads();
    {
        float* dptr = out + 1 + base;
        for (int i = threadIdx.x; i < COMPF; i += TPB) dptr[i] = sbuf[i];
    }

    // loss reduction: warp shuffle -> smem -> one atomic per block
    #pragma unroll
    for (int o = 16; o; o >>= 1) loss += __shfl_xor_sync(0xffffffffu, loss, o);
    if ((threadIdx.x & 31) == 0) sred[threadIdx.x >> 5] = loss;
    __syncthreads();
    if (threadIdx.x == 0) {
        float tot = 0.0f;
        #pragma unroll
        for (int w = 0; w < TPB / 32; w++) tot += sred[w];
        atomicAdd(out, tot * (1.0f / ((float)B_SZ * (float)N_VN)));
    }
}

extern "C" void kernel_launch(void* const* d_in, const int* in_sizes, int n_in,
                              void* d_out, int out_size) {
    const float* llr = (const float*)d_in[0];
    const float* cnw = (const float*)d_in[1];
    const float* chw = (const float*)d_in[2];
    const float* cnb = (const float*)d_in[3];
    float* out = (float*)d_out;
    (void)in_sizes; (void)n_in; (void)out_size;

    ldpc_init<<<1, 32>>>(out);
    ldpc_decode<<<B_SZ * 16, TPB>>>(llr, cnw, chw, cnb, out);
}

// round 9
// speedup vs baseline: 1.9697x; 1.0895x over previous
#include <cuda_runtime.h>

#define B_SZ   128
#define N_VN   24576
#define N_ITERS 10
#define CLIPV  20.0f
#define TPB    64
#define BLKS_PER_ROW 64            // 4096 components / 64 threads
#define COMPF  (TPB * 6)           // 384 floats staged per block
#define SIGNM  0x80000000u
#define L2E    1.4426950408889634f

typedef unsigned long long ull;

__device__ __forceinline__ float mxs_min(float a, float b) {
    float d; asm("min.xorsign.abs.f32 %0, %1, %2;" : "=f"(d) : "f"(a), "f"(b)); return d;
}
__device__ __forceinline__ float mxs_max(float a, float b) {
    float d; asm("max.xorsign.abs.f32 %0, %1, %2;" : "=f"(d) : "f"(a), "f"(b)); return d;
}
__device__ __forceinline__ ull pk2(float lo, float hi) {
    ull r; asm("mov.b64 %0, {%1, %2};" : "=l"(r) : "f"(lo), "f"(hi)); return r;
}
__device__ __forceinline__ void upk2(float& lo, float& hi, ull v) {
    asm("mov.b64 {%0, %1}, %2;" : "=f"(lo), "=f"(hi) : "l"(v));
}
__device__ __forceinline__ ull add2(ull a, ull b) {
    ull r; asm("add.rn.f32x2 %0, %1, %2;" : "=l"(r) : "l"(a), "l"(b)); return r;
}
__device__ __forceinline__ ull mul2(ull a, ull b) {
    ull r; asm("mul.rn.f32x2 %0, %1, %2;" : "=l"(r) : "l"(a), "l"(b)); return r;
}
__device__ __forceinline__ ull fma2(ull a, ull b, ull c) {
    ull r; asm("fma.rn.f32x2 %0, %1, %2, %3;" : "=l"(r) : "l"(a), "l"(b), "l"(c)); return r;
}
__device__ __forceinline__ float ex2f(float x) {
    float r; asm("ex2.approx.ftz.f32 %0, %1;" : "=f"(r) : "f"(x)); return r;
}

__global__ void ldpc_init(float* out) {
    if (threadIdx.x == 0) out[0] = 0.0f;
}

__global__ __launch_bounds__(TPB, 22) void ldpc_decode(
    const float* __restrict__ llr_in,
    const float* __restrict__ cn_weight,
    const float* __restrict__ ch_weight,
    const float* __restrict__ cn_bias,
    float* __restrict__ out)          // out[0]=loss, out+1 = dec [B, N]
{
    __shared__ float sbuf[COMPF];
    __shared__ float sred[TPB / 32];
    __shared__ __align__(16) float itc[N_ITERS][8];   // per-iter constants

    const int b    = blockIdx.x >> 6;
    const int blk  = blockIdx.x & (BLKS_PER_ROW - 1);
    const int base = b * N_VN + blk * COMPF;

    // per-iteration constants computed ONCE (threads 0..9), before the sync
    if (threadIdx.x < N_ITERS) {
        const int it = threadIdx.x;
        const float wch  = ch_weight[it];
        const float wcn  = cn_weight[it];
        const float bcn  = cn_bias[it];
        const float wabs = fabsf(wcn);
        const unsigned wsgnM = __float_as_uint(wcn) & SIGNM;
        itc[it][0] = wch;
        itc[it][1] = wch;                                   // (wch,wch) f32x2 pair
        itc[it][2] = -wcn;                                  // wneg
        itc[it][3] = __uint_as_float(__float_as_uint(bcn) ^ wsgnM);  // pbw
        itc[it][4] = fminf(CLIPV, (CLIPV + bcn) / wabs);    // capA
        itc[it][5] = bcn / wabs;                            // th
    }

    {
        const float4* src = reinterpret_cast<const float4*>(llr_in + base);
        float4* dst = reinterpret_cast<float4*>(sbuf);
        for (int i = threadIdx.x; i < COMPF / 4; i += TPB) dst[i] = src[i];
    }
    __syncthreads();

    ull llr2[3], psum2[3], nc2v2[3][3];     // nc2v = NEGATED c2v, packed pairs
    #pragma unroll
    for (int i = 0; i < 3; i++) {
        llr2[i]  = pk2(sbuf[threadIdx.x * 6 + 2 * i], sbuf[threadIdx.x * 6 + 2 * i + 1]);
        psum2[i] = 0ull;
        nc2v2[0][i] = 0ull; nc2v2[1][i] = 0ull; nc2v2[2][i] = 0ull;
    }

    float sabs  = 0.0f;                     // sum |dec|
    ull   sumd2[3] = {0ull, 0ull, 0ull};    // packed sum dec
    float prodA = 1.0f, prodB = 1.0f;       // prod (1 + exp(-|dec|))
    const ull negone2 = pk2(-1.0f, -1.0f);

    #pragma unroll
    for (int it = 0; it < N_ITERS; ++it) {
        const ull   wch2  = *reinterpret_cast<const ull*>(&itc[it][0]);
        const float wneg  = itc[it][2];
        const unsigned pbw_u = __float_as_uint(itc[it][3]);
        const float capA  = itc[it][4];
        const float th    = itc[it][5];

        ull t2[3];
        #pragma unroll
        for (int i = 0; i < 3; i++) t2[i] = fma2(llr2[i], wch2, psum2[i]);

        #pragma unroll
        for (int k = 0; k < 3; k++) {
            float v[6];
            #pragma unroll
            for (int i = 0; i < 3; i++) {
                const ull v2 = add2(t2[i], nc2v2[k][i]);      // v = t - c2v
                upk2(v[2 * i], v[2 * i + 1], v2);
            }
            // prefix/suffix xorsign LOO-min, cap folded into both scan heads.
            const float q1  = mxs_min(v[0], v[1]);
            const float q1c = mxs_min(q1, capA);
            const float q2  = mxs_min(q1c, v[2]);
            const float q3  = mxs_min(q2,  v[3]);
            const float q4  = mxs_min(q3,  v[4]);
            const float r4  = mxs_min(v[5], v[4]);
            const float r4c = mxs_min(r4, capA);
            const float r3  = mxs_min(r4c, v[3]);
            const float r2  = mxs_min(r3,  v[2]);
            const float r1  = mxs_min(r2,  v[1]);
            float ext[6];
            ext[0] = mxs_max(r1, th);
            ext[1] = mxs_max(mxs_min(v[0], r2), th);
            ext[2] = mxs_max(mxs_min(q1c, r3), th);
            ext[3] = mxs_max(mxs_min(q2, r4c), th);
            ext[4] = mxs_max(mxs_min(q3, v[5]), th);
            ext[5] = mxs_max(q4, th);

            float nc[6];
            #pragma unroll
            for (int j = 0; j < 6; j++) {
                // nc2v = -c2v = -sgn*(|ext|*wabs - bcn); sgn carried by ext & wcn
                const float aj = __uint_as_float(pbw_u ^ (__float_as_uint(ext[j]) & SIGNM));
                nc[j] = fmaf(ext[j], wneg, aj);
            }
            #pragma unroll
            for (int i = 0; i < 3; i++) nc2v2[k][i] = pk2(nc[2 * i], nc[2 * i + 1]);
        }

        // marginals + BCE pieces:
        //   sum relu(-d) deferred via (sum|d| - sum d)/2 ; log via products
        #pragma unroll
        for (int i = 0; i < 3; i++) {
            const ull nsum = add2(add2(nc2v2[0][i], nc2v2[1][i]), nc2v2[2][i]);
            psum2[i] = mul2(nsum, negone2);                   // +sum
            const ull d2 = add2(llr2[i], psum2[i]);
            sumd2[i] = add2(sumd2[i], d2);
            float d0, d1;
            upk2(d0, d1, d2);
            sabs += fabsf(d0);                                // FADD |mod|
            sabs += fabsf(d1);
            const float e0 = ex2f(fabsf(d0) * (-L2E));        // FMUL |mod|,imm
            const float e1 = ex2f(fabsf(d1) * (-L2E));
            prodA = fmaf(prodA, e0, prodA);                   // *= (1 + e)
            prodB = fmaf(prodB, e1, prodB);
        }
    }

    float sd = 0.0f;
    #pragma unroll
    for (int i = 0; i < 3; i++) {
        float s0, s1; upk2(s0, s1, sumd2[i]);
        sd += s0 + s1;
    }
    float loss = fmaf(0.5f, sabs - sd,                          // sum relu(-dec)
                 0.6931471805599453f * (__log2f(prodA) + __log2f(prodB)));

    // recompute dec, overwrite own smem cells, then coalesced global write
    #pragma unroll
    for (int i = 0; i < 3; i++) {
        const ull d2 = add2(llr2[i], psum2[i]);
        float d0, d1;
        upk2(d0, d1, d2);
        sbuf[threadIdx.x * 6 + 2 * i]     = d0;
        sbuf[threadIdx.x * 6 + 2 * i + 1] = d1;
    }
    __syncthreads();
    {
        float* dptr = out + 1 + base;
        for (int i = threadIdx.x; i < COMPF; i += TPB) dptr[i] = sbuf[i];
    }

    // loss reduction: warp shuffle -> smem -> one atomic per block
    #pragma unroll
    for (int o = 16; o; o >>= 1) loss += __shfl_xor_sync(0xffffffffu, loss, o);
    if ((threadIdx.x & 31) == 0) sred[threadIdx.x >> 5] = loss;
    __syncthreads();
    if (threadIdx.x == 0) {
        float tot = 0.0f;
        #pragma unroll
        for (int w = 0; w < TPB / 32; w++) tot += sred[w];
        atomicAdd(out, tot * (1.0f / ((float)B_SZ * (float)N_VN)));
    }
}

extern "C" void kernel_launch(void* const* d_in, const int* in_sizes, int n_in,
                              void* d_out, int out_size) {
    const float* llr = (const float*)d_in[0];
    const float* cnw = (const float*)d_in[1];
    const float* chw = (const float*)d_in[2];
    const float* cnb = (const float*)d_in[3];
    float* out = (float*)d_out;
    (void)in_sizes; (void)n_in; (void)out_size;

    ldpc_init<<<1, 32>>>(out);
    ldpc_decode<<<B_SZ * BLKS_PER_ROW, TPB>>>(llr, cnw, chw, cnb, out);
}

// round 14
// speedup vs baseline: 1.9889x; 1.0097x over previous
#include <cuda_runtime.h>

#define B_SZ   128
#define N_VN   24576
#define N_ITERS 10
#define CLIPV  20.0f
#define TPB    64
#define BLKS_PER_ROW 64            // 4096 components / 64 threads
#define COMPF  (TPB * 6)           // 384 floats staged per block
#define SIGNM  0x80000000u
#define L2E    1.4426950408889634f

typedef unsigned long long ull;

__device__ __forceinline__ float mxs_min(float a, float b) {
    float d; asm("min.xorsign.abs.f32 %0, %1, %2;" : "=f"(d) : "f"(a), "f"(b)); return d;
}
__device__ __forceinline__ float mxs_max(float a, float b) {
    float d; asm("max.xorsign.abs.f32 %0, %1, %2;" : "=f"(d) : "f"(a), "f"(b)); return d;
}
__device__ __forceinline__ ull pk2(float lo, float hi) {
    ull r; asm("mov.b64 %0, {%1, %2};" : "=l"(r) : "f"(lo), "f"(hi)); return r;
}
__device__ __forceinline__ void upk2(float& lo, float& hi, ull v) {
    asm("mov.b64 {%0, %1}, %2;" : "=f"(lo), "=f"(hi) : "l"(v));
}
__device__ __forceinline__ ull add2(ull a, ull b) {
    ull r; asm("add.rn.f32x2 %0, %1, %2;" : "=l"(r) : "l"(a), "l"(b)); return r;
}
__device__ __forceinline__ ull fma2(ull a, ull b, ull c) {
    ull r; asm("fma.rn.f32x2 %0, %1, %2, %3;" : "=l"(r) : "l"(a), "l"(b), "l"(c)); return r;
}
__device__ __forceinline__ float ex2f(float x) {
    float r; asm("ex2.approx.ftz.f32 %0, %1;" : "=f"(r) : "f"(x)); return r;
}

__global__ void ldpc_init(float* out) {
    if (threadIdx.x == 0) out[0] = 0.0f;
}

__global__ __launch_bounds__(TPB, 25) void ldpc_decode(
    const float* __restrict__ llr_in,
    const float* __restrict__ cn_weight,
    const float* __restrict__ ch_weight,
    const float* __restrict__ cn_bias,
    float* __restrict__ out)          // out[0]=loss, out+1 = dec [B, N]
{
    __shared__ float sbuf[COMPF];
    __shared__ float sred[TPB / 32];
    __shared__ __align__(16) float itc[N_ITERS][8];   // per-iter constants

    const int b    = blockIdx.x >> 6;
    const int blk  = blockIdx.x & (BLKS_PER_ROW - 1);
    const int base = b * N_VN + blk * COMPF;

    // per-iteration constants computed ONCE (threads 0..9), before the sync
    if (threadIdx.x < N_ITERS) {
        const int it = threadIdx.x;
        const float wch  = ch_weight[it];
        const float wcn  = cn_weight[it];
        const float bcn  = cn_bias[it];
        const float wabs = fabsf(wcn);
        const unsigned wsgnM = __float_as_uint(wcn) & SIGNM;
        itc[it][0] = wch;
        itc[it][1] = wch;                                   // (wch,wch) f32x2 pair
        itc[it][2] = wcn;                                   // wpos (c2v positive now)
        itc[it][3] = __uint_as_float(__float_as_uint(-bcn) ^ wsgnM); // nbw
        itc[it][4] = fminf(CLIPV, (CLIPV + bcn) / wabs);    // capA
        itc[it][5] = bcn / wabs;                            // th
    }

    {
        const float4* src = reinterpret_cast<const float4*>(llr_in + base);
        float4* dst = reinterpret_cast<float4*>(sbuf);
        for (int i = threadIdx.x; i < COMPF / 4; i += TPB) dst[i] = src[i];
    }
    __syncthreads();

    ull llr2[3], psum2[3], c2v2[3][3];      // c2v stored POSITIVE, packed pairs
    #pragma unroll
    for (int i = 0; i < 3; i++) {
        llr2[i]  = pk2(sbuf[threadIdx.x * 6 + 2 * i], sbuf[threadIdx.x * 6 + 2 * i + 1]);
        psum2[i] = 0ull;
        c2v2[0][i] = 0ull; c2v2[1][i] = 0ull; c2v2[2][i] = 0ull;
    }

    float sabs  = 0.0f;                     // sum |dec|
    ull   sumd2[3] = {0ull, 0ull, 0ull};    // packed sum dec
    float prodA = 1.0f, prodB = 1.0f;       // prod (1 + exp(-|dec|))
    const ull negone2 = pk2(-1.0f, -1.0f);

    #pragma unroll
    for (int it = 0; it < N_ITERS; ++it) {
        const ull   wch2  = *reinterpret_cast<const ull*>(&itc[it][0]);
        const float wpos  = itc[it][2];
        const unsigned nbw_u = __float_as_uint(itc[it][3]);
        const float capA  = itc[it][4];
        const float th    = itc[it][5];

        ull t2[3];
        #pragma unroll
        for (int i = 0; i < 3; i++) t2[i] = fma2(llr2[i], wch2, psum2[i]);

        #pragma unroll
        for (int k = 0; k < 3; k++) {
            float v[6];
            #pragma unroll
            for (int i = 0; i < 3; i++) {
                // v = t - c2v  (one packed fma, c2v stays positive)
                const ull v2 = fma2(c2v2[k][i], negone2, t2[i]);
                upk2(v[2 * i], v[2 * i + 1], v2);
            }
            // prefix/suffix xorsign LOO-min, cap folded into both scan heads.
            const float q1  = mxs_min(v[0], v[1]);
            const float q1c = mxs_min(q1, capA);
            const float q2  = mxs_min(q1c, v[2]);
            const float q3  = mxs_min(q2,  v[3]);
            const float q4  = mxs_min(q3,  v[4]);
            const float r4  = mxs_min(v[5], v[4]);
            const float r4c = mxs_min(r4, capA);
            const float r3  = mxs_min(r4c, v[3]);
            const float r2  = mxs_min(r3,  v[2]);
            const float r1  = mxs_min(r2,  v[1]);
            float ext[6];
            ext[0] = mxs_max(r1, th);
            ext[1] = mxs_max(mxs_min(v[0], r2), th);
            ext[2] = mxs_max(mxs_min(q1c, r3), th);
            ext[3] = mxs_max(mxs_min(q2, r4c), th);
            ext[4] = mxs_max(mxs_min(q3, v[5]), th);
            ext[5] = mxs_max(q4, th);

            float nc[6];
            #pragma unroll
            for (int j = 0; j < 6; j++) {
                // c2v = sgn*(|ext|*wabs - bcn); sgn = sign(ext) xor sign(wcn),
                // carried by the product and the sign-matched addend
                const float aj = __uint_as_float(nbw_u ^ (__float_as_uint(ext[j]) & SIGNM));
                nc[j] = fmaf(ext[j], wpos, aj);
            }
            #pragma unroll
            for (int i = 0; i < 3; i++) c2v2[k][i] = pk2(nc[2 * i], nc[2 * i + 1]);
        }

        // marginals + BCE pieces:
        //   sum relu(-d) deferred via (sum|d| - sum d)/2 ; log via products
        #pragma unroll
        for (int i = 0; i < 3; i++) {
            psum2[i] = add2(add2(c2v2[0][i], c2v2[1][i]), c2v2[2][i]);  // +sum
            const ull d2 = add2(llr2[i], psum2[i]);
            sumd2[i] = add2(sumd2[i], d2);
            float d0, d1;
            upk2(d0, d1, d2);
            sabs += fabsf(d0);                                // FADD |mod|
            sabs += fabsf(d1);
            const float e0 = ex2f(fabsf(d0) * (-L2E));        // FMUL |mod|,imm
            const float e1 = ex2f(fabsf(d1) * (-L2E));
            prodA = fmaf(prodA, e0, prodA);                   // *= (1 + e)
            prodB = fmaf(prodB, e1, prodB);
        }
    }

    float sd = 0.0f;
    #pragma unroll
    for (int i = 0; i < 3; i++) {
        float s0, s1; upk2(s0, s1, sumd2[i]);
        sd += s0 + s1;
    }
    float loss = fmaf(0.5f, sabs - sd,                          // sum relu(-dec)
                 0.6931471805599453f * (__log2f(prodA) + __log2f(prodB)));

    // recompute dec, overwrite own smem cells, then coalesced global write
    #pragma unroll
    for (int i = 0; i < 3; i++) {
        const ull d2 = add2(llr2[i], psum2[i]);
        float d0, d1;
        upk2(d0, d1, d2);
        sbuf[threadIdx.x * 6 + 2 * i]     = d0;
        sbuf[threadIdx.x * 6 + 2 * i + 1] = d1;
    }
    __syncthreads();
    {
        float* dptr = out + 1 + base;
        for (int i = threadIdx.x; i < COMPF; i += TPB) dptr[i] = sbuf[i];
    }

    // loss reduction: warp shuffle -> smem -> one atomic per block
    #pragma unroll
    for (int o = 16; o; o >>= 1) loss += __shfl_xor_sync(0xffffffffu, loss, o);
    if ((threadIdx.x & 31) == 0) sred[threadIdx.x >> 5] = loss;
    __syncthreads();
    if (threadIdx.x == 0) {
        float tot = 0.0f;
        #pragma unroll
        for (int w = 0; w < TPB / 32; w++) tot += sred[w];
        atomicAdd(out, tot * (1.0f / ((float)B_SZ * (float)N_VN)));
    }
}

extern "C" void kernel_launch(void* const* d_in, const int* in_sizes, int n_in,
                              void* d_out, int out_size) {
    const float* llr = (const float*)d_in[0];
    const float* cnw = (const float*)d_in[1];
    const float* chw = (const float*)d_in[2];
    const float* cnb = (const float*)d_in[3];
    float* out = (float*)d_out;
    (void)in_sizes; (void)n_in; (void)out_size;

    ldpc_init<<<1, 32>>>(out);
    ldpc_decode<<<B_SZ * BLKS_PER_ROW, TPB>>>(llr, cnw, chw, cnb, out);
}